// round 8
// baseline (speedup 1.0000x reference)
#include <cuda_runtime.h>
#include <cuda_fp16.h>
#include <stdint.h>
#include <math.h>

#define F_IN 128
#define HID  16
#define NC   10
#define CP   12
#define N_MAX 100000
#define E_MAX 1600000
#define SCAN_BLK 1024

// ---------------- scratch (allocation-free, aligned) ----------------
// interleaved fp16 tables: per node 64B block; half[2j]=a0[j], half[2j+1]=ad[j]
__device__ __align__(16) __half g_aqh[(N_MAX + 1) * 32];
// per node: pairs (b0[c], bd[c]) c=0..11 in halves 0..23, rest pad
__device__ __align__(16) __half g_bqh[(N_MAX + 1) * 32];
__device__ __align__(16) float g_base1[N_MAX * HID];   // x @ root1 + b1
__device__ __align__(16) float g_h    [N_MAX * HID];   // ELU(layer1)
__device__ __align__(16) float g_base2[N_MAX * CP];    // h @ root2 + b2
// padded CSR
__device__ int g_cnt   [N_MAX];          // true degree
__device__ int g_rowoff[N_MAX + 1];      // padded row offsets (multiples of 4)
__device__ int g_cur   [N_MAX];
__device__ int g_bsum  [SCAN_BLK];
__device__ __align__(16) int2 g_edge[E_MAX + 3 * N_MAX + 4];  // {src, w_bits}

static __device__ __forceinline__ unsigned int pack_h2(float a, float b) {
    __half2 h = __floats2half2_rn(a, b);
    return *reinterpret_cast<unsigned int*>(&h);
}

static __device__ __forceinline__ float4 acc_edge(float4 acc, uint4 g, float w) {
    float2 p0 = __half22float2(*reinterpret_cast<__half2*>(&g.x));
    float2 p1 = __half22float2(*reinterpret_cast<__half2*>(&g.y));
    float2 p2 = __half22float2(*reinterpret_cast<__half2*>(&g.z));
    float2 p3 = __half22float2(*reinterpret_cast<__half2*>(&g.w));
    acc.x += fmaf(w, p0.y, p0.x);
    acc.y += fmaf(w, p1.y, p1.x);
    acc.z += fmaf(w, p2.y, p2.x);
    acc.w += fmaf(w, p3.y, p3.x);
    return acc;
}

// ---------------- init: zero counters, fill pad edges, zero sentinel node ----
__global__ void init_kernel(int N, int P) {
    int stride = gridDim.x * blockDim.x;
    for (int i = blockIdx.x * blockDim.x + threadIdx.x; i < P; i += stride) {
        if (i < N) g_cnt[i] = 0;
        g_edge[i] = make_int2(N, 0);           // sentinel src, w=0
    }
    if (blockIdx.x == 0 && threadIdx.x < 32) {
        g_aqh[(size_t)N * 32 + threadIdx.x] = __float2half(0.f);
        g_bqh[(size_t)N * 32 + threadIdx.x] = __float2half(0.f);
    }
}

__global__ void hist_kernel(const int* __restrict__ ei, int E) {
    int e = blockIdx.x * blockDim.x + threadIdx.x;
    if (e >= E) return;
    atomicAdd(&g_cnt[__ldg(&ei[E + e])], 1);
}

// shuffle-based block scan of padded counts
__global__ __launch_bounds__(SCAN_BLK)
void scan1_kernel(int N) {
    int i = blockIdx.x * SCAN_BLK + threadIdx.x;
    int lane = threadIdx.x & 31, wid = threadIdx.x >> 5;
    int c = (i < N) ? g_cnt[i] : 0;
    int v = (c + 3) & ~3;                      // pad row to multiple of 4
    int x = v;
#pragma unroll
    for (int off = 1; off < 32; off <<= 1) {
        int y = __shfl_up_sync(0xFFFFFFFFu, x, off);
        if (lane >= off) x += y;
    }
    __shared__ int ws[32];
    if (lane == 31) ws[wid] = x;
    __syncthreads();
    if (wid == 0) {
        int t = ws[lane];
#pragma unroll
        for (int off = 1; off < 32; off <<= 1) {
            int y = __shfl_up_sync(0xFFFFFFFFu, t, off);
            if (lane >= off) t += y;
        }
        ws[lane] = t;
    }
    __syncthreads();
    int base = (wid > 0) ? ws[wid - 1] : 0;
    if (i < N) g_rowoff[i] = base + x - v;     // block-local exclusive
    if (threadIdx.x == 0) g_bsum[blockIdx.x] = ws[31];
}

// single-warp scan of block sums (nblk <= 1024); also writes rowoff[N] = total
__global__ void scan2_kernel(int nblk, int N) {
    if (threadIdx.x >= 32) return;
    int lane = threadIdx.x;
    int carry = 0;
    for (int base = 0; base < nblk; base += 32) {
        int idx = base + lane;
        int v = (idx < nblk) ? g_bsum[idx] : 0;
        int x = v;
#pragma unroll
        for (int off = 1; off < 32; off <<= 1) {
            int y = __shfl_up_sync(0xFFFFFFFFu, x, off);
            if (lane >= off) x += y;
        }
        if (idx < nblk) g_bsum[idx] = carry + x - v;
        carry += __shfl_sync(0xFFFFFFFFu, x, 31);
    }
    if (lane == 0) g_rowoff[N] = carry;
}

__global__ __launch_bounds__(SCAN_BLK)
void scan3_kernel(int N) {
    int i = blockIdx.x * SCAN_BLK + threadIdx.x;
    if (i < N) {
        int v = g_rowoff[i] + g_bsum[blockIdx.x];
        g_rowoff[i] = v;
        g_cur[i]    = v;
    }
}

__global__ void reorder_kernel(const int* __restrict__ ei,
                               const float* __restrict__ attr, int E) {
    int e = blockIdx.x * blockDim.x + threadIdx.x;
    if (e >= E) return;
    int s = __ldg(&ei[e]);
    int d = __ldg(&ei[E + e]);
    float w = __ldg(&attr[e]);
    int pos = atomicAdd(&g_cur[d], 1);
    g_edge[pos] = make_int2(s, __float_as_int(w));
}

// ---------------- layer-1 node transform ----------------
__global__ __launch_bounds__(128)
void node1_kernel(const float* __restrict__ x,
                  const float* __restrict__ W1,
                  const float* __restrict__ root1,
                  const float* __restrict__ b1, int N)
{
    __shared__ float sW0[F_IN * HID];
    __shared__ float sWd[F_IN * HID];
    __shared__ float sR [F_IN * HID];
    for (int i = threadIdx.x; i < F_IN * HID; i += blockDim.x) {
        float w0 = W1[i];
        sW0[i] = w0;
        sWd[i] = W1[F_IN * HID + i] - w0;
        sR [i] = root1[i];
    }
    __syncthreads();

    int n = blockIdx.x * blockDim.x + threadIdx.x;
    if (n >= N) return;

    float acc0[HID], accd[HID], accr[HID];
#pragma unroll
    for (int j = 0; j < HID; j++) { acc0[j] = 0.f; accd[j] = 0.f; accr[j] = 0.f; }

    const float4* xr = reinterpret_cast<const float4*>(x + (size_t)n * F_IN);
#pragma unroll 4
    for (int k4 = 0; k4 < F_IN / 4; k4++) {
        float4 xv = __ldg(&xr[k4]);
        float xs[4] = { xv.x, xv.y, xv.z, xv.w };
#pragma unroll
        for (int kk = 0; kk < 4; kk++) {
            float xk  = xs[kk];
            int  base = (k4 * 4 + kk) * HID;
#pragma unroll
            for (int j4 = 0; j4 < HID / 4; j4++) {
                float4 w0 = *reinterpret_cast<const float4*>(&sW0[base + j4 * 4]);
                float4 wd = *reinterpret_cast<const float4*>(&sWd[base + j4 * 4]);
                float4 wr = *reinterpret_cast<const float4*>(&sR [base + j4 * 4]);
                acc0[j4*4+0] += xk * w0.x; acc0[j4*4+1] += xk * w0.y;
                acc0[j4*4+2] += xk * w0.z; acc0[j4*4+3] += xk * w0.w;
                accd[j4*4+0] += xk * wd.x; accd[j4*4+1] += xk * wd.y;
                accd[j4*4+2] += xk * wd.z; accd[j4*4+3] += xk * wd.w;
                accr[j4*4+0] += xk * wr.x; accr[j4*4+1] += xk * wr.y;
                accr[j4*4+2] += xk * wr.z; accr[j4*4+3] += xk * wr.w;
            }
        }
    }
    // interleaved pack: half[2j]=a0[j], half[2j+1]=ad[j]
    uint4 u0, u1, u2, u3;
    u0.x = pack_h2(acc0[0],  accd[0]);  u0.y = pack_h2(acc0[1],  accd[1]);
    u0.z = pack_h2(acc0[2],  accd[2]);  u0.w = pack_h2(acc0[3],  accd[3]);
    u1.x = pack_h2(acc0[4],  accd[4]);  u1.y = pack_h2(acc0[5],  accd[5]);
    u1.z = pack_h2(acc0[6],  accd[6]);  u1.w = pack_h2(acc0[7],  accd[7]);
    u2.x = pack_h2(acc0[8],  accd[8]);  u2.y = pack_h2(acc0[9],  accd[9]);
    u2.z = pack_h2(acc0[10], accd[10]); u2.w = pack_h2(acc0[11], accd[11]);
    u3.x = pack_h2(acc0[12], accd[12]); u3.y = pack_h2(acc0[13], accd[13]);
    u3.z = pack_h2(acc0[14], accd[14]); u3.w = pack_h2(acc0[15], accd[15]);
    uint4* dst = reinterpret_cast<uint4*>(&g_aqh[(size_t)n * 32]);
    dst[0] = u0; dst[1] = u1; dst[2] = u2; dst[3] = u3;

#pragma unroll
    for (int j4 = 0; j4 < HID / 4; j4++) {
        *reinterpret_cast<float4*>(&g_base1[(size_t)n * HID + j4 * 4]) =
            make_float4(accr[j4*4]   + b1[j4*4],   accr[j4*4+1] + b1[j4*4+1],
                        accr[j4*4+2] + b1[j4*4+2], accr[j4*4+3] + b1[j4*4+3]);
    }
}

// ---------------- layer-1 aggregation (atomic-free) + ELU --------------------
__global__ void agg1_kernel(int N)
{
    int t = blockIdx.x * blockDim.x + threadIdx.x;
    int n = t >> 2;
    int r = t & 3;
    if (n >= N) return;

    int beg = __ldg(&g_rowoff[n]);
    int end = __ldg(&g_rowoff[n + 1]);

    float4 acc = make_float4(0.f, 0.f, 0.f, 0.f);
    for (int i = beg; i < end; i += 4) {
        int4 e01 = __ldg(reinterpret_cast<const int4*>(&g_edge[i]));
        int4 e23 = __ldg(reinterpret_cast<const int4*>(&g_edge[i + 2]));
        uint4 g0 = __ldg(reinterpret_cast<const uint4*>(&g_aqh[(size_t)e01.x * 32 + r * 8]));
        uint4 g1 = __ldg(reinterpret_cast<const uint4*>(&g_aqh[(size_t)e01.z * 32 + r * 8]));
        uint4 g2 = __ldg(reinterpret_cast<const uint4*>(&g_aqh[(size_t)e23.x * 32 + r * 8]));
        uint4 g3 = __ldg(reinterpret_cast<const uint4*>(&g_aqh[(size_t)e23.z * 32 + r * 8]));
        acc = acc_edge(acc, g0, __int_as_float(e01.y));
        acc = acc_edge(acc, g1, __int_as_float(e01.w));
        acc = acc_edge(acc, g2, __int_as_float(e23.y));
        acc = acc_edge(acc, g3, __int_as_float(e23.w));
    }

    float inv = 1.f / fmaxf((float)__ldg(&g_cnt[n]), 1.f);
    float4 bs = *reinterpret_cast<const float4*>(&g_base1[(size_t)n * HID + r * 4]);
    float v[4] = { acc.x * inv + bs.x, acc.y * inv + bs.y,
                   acc.z * inv + bs.z, acc.w * inv + bs.w };
    float4 h;
    h.x = (v[0] > 0.f) ? v[0] : expm1f(v[0]);
    h.y = (v[1] > 0.f) ? v[1] : expm1f(v[1]);
    h.z = (v[2] > 0.f) ? v[2] : expm1f(v[2]);
    h.w = (v[3] > 0.f) ? v[3] : expm1f(v[3]);
    *reinterpret_cast<float4*>(&g_h[(size_t)n * HID + r * 4]) = h;
}

// ---------------- layer-2 node transform ----------------
__global__ __launch_bounds__(128)
void node2_kernel(const float* __restrict__ W2,
                  const float* __restrict__ root2,
                  const float* __restrict__ b2, int N)
{
    __shared__ float sB0[HID * CP];
    __shared__ float sBd[HID * CP];
    __shared__ float sR [HID * CP];
    __shared__ float sb2[CP];
    for (int i = threadIdx.x; i < HID * CP; i += blockDim.x) {
        int j = i / CP, c = i - j * CP;
        float w0 = (c < NC) ? W2[j * NC + c] : 0.f;
        float w1 = (c < NC) ? W2[HID * NC + j * NC + c] : 0.f;
        sB0[i] = w0;
        sBd[i] = w1 - w0;
        sR [i] = (c < NC) ? root2[j * NC + c] : 0.f;
    }
    if (threadIdx.x < CP) sb2[threadIdx.x] = (threadIdx.x < NC) ? b2[threadIdx.x] : 0.f;
    __syncthreads();

    int n = blockIdx.x * blockDim.x + threadIdx.x;
    if (n >= N) return;

    float h[HID];
#pragma unroll
    for (int j4 = 0; j4 < HID / 4; j4++) {
        float4 hv = *reinterpret_cast<const float4*>(&g_h[(size_t)n * HID + j4 * 4]);
        h[j4*4+0] = hv.x; h[j4*4+1] = hv.y; h[j4*4+2] = hv.z; h[j4*4+3] = hv.w;
    }

    float o0[CP], od[CP], orr[CP];
#pragma unroll
    for (int c = 0; c < CP; c++) { o0[c] = 0.f; od[c] = 0.f; orr[c] = 0.f; }
#pragma unroll
    for (int j = 0; j < HID; j++) {
        float hj = h[j];
#pragma unroll
        for (int c4 = 0; c4 < CP / 4; c4++) {
            float4 w0 = *reinterpret_cast<const float4*>(&sB0[j * CP + c4 * 4]);
            float4 wd = *reinterpret_cast<const float4*>(&sBd[j * CP + c4 * 4]);
            float4 wr = *reinterpret_cast<const float4*>(&sR [j * CP + c4 * 4]);
            o0[c4*4+0] += hj * w0.x; o0[c4*4+1] += hj * w0.y;
            o0[c4*4+2] += hj * w0.z; o0[c4*4+3] += hj * w0.w;
            od[c4*4+0] += hj * wd.x; od[c4*4+1] += hj * wd.y;
            od[c4*4+2] += hj * wd.z; od[c4*4+3] += hj * wd.w;
            orr[c4*4+0] += hj * wr.x; orr[c4*4+1] += hj * wr.y;
            orr[c4*4+2] += hj * wr.z; orr[c4*4+3] += hj * wr.w;
        }
    }
    // interleaved pack: half[2c]=b0[c], half[2c+1]=bd[c], c=0..11
    uint4 u0, u1, u2;
    u0.x = pack_h2(o0[0],  od[0]);  u0.y = pack_h2(o0[1],  od[1]);
    u0.z = pack_h2(o0[2],  od[2]);  u0.w = pack_h2(o0[3],  od[3]);
    u1.x = pack_h2(o0[4],  od[4]);  u1.y = pack_h2(o0[5],  od[5]);
    u1.z = pack_h2(o0[6],  od[6]);  u1.w = pack_h2(o0[7],  od[7]);
    u2.x = pack_h2(o0[8],  od[8]);  u2.y = pack_h2(o0[9],  od[9]);
    u2.z = pack_h2(o0[10], od[10]); u2.w = pack_h2(o0[11], od[11]);
    uint4* dst = reinterpret_cast<uint4*>(&g_bqh[(size_t)n * 32]);
    dst[0] = u0; dst[1] = u1; dst[2] = u2;

#pragma unroll
    for (int c4 = 0; c4 < CP / 4; c4++) {
        *reinterpret_cast<float4*>(&g_base2[(size_t)n * CP + c4 * 4]) =
            make_float4(orr[c4*4]   + sb2[c4*4],   orr[c4*4+1] + sb2[c4*4+1],
                        orr[c4*4+2] + sb2[c4*4+2], orr[c4*4+3] + sb2[c4*4+3]);
    }
}

// ---------------- layer-2 aggregation (atomic-free) + output -----------------
__global__ void agg2_kernel(float* __restrict__ out, int N)
{
    int t = blockIdx.x * blockDim.x + threadIdx.x;
    int n = t >> 2;
    int r = t & 3;
    if (n >= N || r == 3) return;

    int beg = __ldg(&g_rowoff[n]);
    int end = __ldg(&g_rowoff[n + 1]);

    float4 acc = make_float4(0.f, 0.f, 0.f, 0.f);
    for (int i = beg; i < end; i += 4) {
        int4 e01 = __ldg(reinterpret_cast<const int4*>(&g_edge[i]));
        int4 e23 = __ldg(reinterpret_cast<const int4*>(&g_edge[i + 2]));
        uint4 g0 = __ldg(reinterpret_cast<const uint4*>(&g_bqh[(size_t)e01.x * 32 + r * 8]));
        uint4 g1 = __ldg(reinterpret_cast<const uint4*>(&g_bqh[(size_t)e01.z * 32 + r * 8]));
        uint4 g2 = __ldg(reinterpret_cast<const uint4*>(&g_bqh[(size_t)e23.x * 32 + r * 8]));
        uint4 g3 = __ldg(reinterpret_cast<const uint4*>(&g_bqh[(size_t)e23.z * 32 + r * 8]));
        acc = acc_edge(acc, g0, __int_as_float(e01.y));
        acc = acc_edge(acc, g1, __int_as_float(e01.w));
        acc = acc_edge(acc, g2, __int_as_float(e23.y));
        acc = acc_edge(acc, g3, __int_as_float(e23.w));
    }

    float inv = 1.f / fmaxf((float)__ldg(&g_cnt[n]), 1.f);
    float4 bs = *reinterpret_cast<const float4*>(&g_base2[(size_t)n * CP + r * 4]);
    float o[4] = { acc.x * inv + bs.x, acc.y * inv + bs.y,
                   acc.z * inv + bs.z, acc.w * inv + bs.w };

    float* op = out + (size_t)n * NC + r * 4;
    int lim = NC - r * 4;                 // 4,4,2 for r=0,1,2
#pragma unroll
    for (int q = 0; q < 4; q++)
        if (q < lim) op[q] = o[q];
}

// ---------------- launcher ----------------
extern "C" void kernel_launch(void* const* d_in, const int* in_sizes, int n_in,
                              void* d_out, int out_size)
{
    const float* x     = (const float*)d_in[0];
    const int*   ei    = (const int*)d_in[1];
    const float* attr  = (const float*)d_in[2];
    const float* W1    = (const float*)d_in[3];
    const float* root1 = (const float*)d_in[4];
    const float* b1    = (const float*)d_in[5];
    const float* W2    = (const float*)d_in[6];
    const float* root2 = (const float*)d_in[7];
    const float* b2    = (const float*)d_in[8];
    float*       out   = (float*)d_out;

    int N = in_sizes[0] / F_IN;
    int E = in_sizes[2];
    int P = E + 3 * N + 4;                 // padded CSR upper bound
    int nblk = (N + SCAN_BLK - 1) / SCAN_BLK;

    // CSR build (shared by both layers)
    init_kernel<<<512, 256>>>(N, P);
    hist_kernel<<<(E + 255) / 256, 256>>>(ei, E);
    scan1_kernel<<<nblk, SCAN_BLK>>>(N);
    scan2_kernel<<<1, 32>>>(nblk, N);
    scan3_kernel<<<nblk, SCAN_BLK>>>(N);
    reorder_kernel<<<(E + 255) / 256, 256>>>(ei, attr, E);

    // layer 1
    node1_kernel<<<(N + 127) / 128, 128>>>(x, W1, root1, b1, N);
    agg1_kernel<<<(N * 4 + 255) / 256, 256>>>(N);

    // layer 2
    node2_kernel<<<(N + 127) / 128, 128>>>(W2, root2, b2, N);
    agg2_kernel<<<(N * 4 + 255) / 256, 256>>>(out, N);
}

// round 10
// speedup vs baseline: 1.0883x; 1.0883x over previous
#include <cuda_runtime.h>
#include <cuda_fp16.h>
#include <stdint.h>
#include <math.h>

#define F_IN 128
#define HID  16
#define NC   10
#define CP   12
#define N_MAX 100000
#define E_MAX 1600000

// ---------------- scratch (allocation-free, aligned) ----------------
// interleaved fp16 tables: per node 64B block; half[2j]=a0[j], half[2j+1]=ad[j]
__device__ __align__(16) __half g_aqh[N_MAX * 32];
// per node: pairs (b0[c], bd[c]) c=0..11 in halves 0..23, rest pad (48B used)
__device__ __align__(16) __half g_bqh[N_MAX * 32];
__device__ __align__(16) float g_base1[N_MAX * HID];  // x @ root1 + b1
__device__ __align__(16) float g_agg1 [N_MAX * HID];
__device__ __align__(16) float g_deg  [N_MAX];
__device__ __align__(16) float g_base2[N_MAX * CP];   // h @ root2 + b2
__device__ __align__(16) float g_agg2 [N_MAX * CP];

static __device__ __forceinline__ unsigned int pack_h2(float a, float b) {
    __half2 h = __floats2half2_rn(a, b);
    return *reinterpret_cast<unsigned int*>(&h);
}

// ---------------- layer-1 node transform (+ zero accumulators) ---------------
__global__ __launch_bounds__(128)
void node1_kernel(const float* __restrict__ x,
                  const float* __restrict__ W1,
                  const float* __restrict__ root1,
                  const float* __restrict__ b1, int N)
{
    __shared__ float sW0[F_IN * HID];
    __shared__ float sWd[F_IN * HID];
    __shared__ float sR [F_IN * HID];
    for (int i = threadIdx.x; i < F_IN * HID; i += blockDim.x) {
        float w0 = W1[i];
        sW0[i] = w0;
        sWd[i] = W1[F_IN * HID + i] - w0;
        sR [i] = root1[i];
    }
    __syncthreads();

    int n = blockIdx.x * blockDim.x + threadIdx.x;
    if (n >= N) return;

    // zero this node's accumulators (replaces zero_kernel; runs before edge passes)
    float4 z4 = make_float4(0.f, 0.f, 0.f, 0.f);
#pragma unroll
    for (int j4 = 0; j4 < HID / 4; j4++)
        *reinterpret_cast<float4*>(&g_agg1[(size_t)n * HID + j4 * 4]) = z4;
#pragma unroll
    for (int c4 = 0; c4 < CP / 4; c4++)
        *reinterpret_cast<float4*>(&g_agg2[(size_t)n * CP + c4 * 4]) = z4;
    g_deg[n] = 0.f;

    float acc0[HID], accd[HID], accr[HID];
#pragma unroll
    for (int j = 0; j < HID; j++) { acc0[j] = 0.f; accd[j] = 0.f; accr[j] = 0.f; }

    const float4* xr = reinterpret_cast<const float4*>(x + (size_t)n * F_IN);
#pragma unroll 4
    for (int k4 = 0; k4 < F_IN / 4; k4++) {
        float4 xv = __ldg(&xr[k4]);
        float xs[4] = { xv.x, xv.y, xv.z, xv.w };
#pragma unroll
        for (int kk = 0; kk < 4; kk++) {
            float xk  = xs[kk];
            int  base = (k4 * 4 + kk) * HID;
#pragma unroll
            for (int j4 = 0; j4 < HID / 4; j4++) {
                float4 w0 = *reinterpret_cast<const float4*>(&sW0[base + j4 * 4]);
                float4 wd = *reinterpret_cast<const float4*>(&sWd[base + j4 * 4]);
                float4 wr = *reinterpret_cast<const float4*>(&sR [base + j4 * 4]);
                acc0[j4*4+0] += xk * w0.x; acc0[j4*4+1] += xk * w0.y;
                acc0[j4*4+2] += xk * w0.z; acc0[j4*4+3] += xk * w0.w;
                accd[j4*4+0] += xk * wd.x; accd[j4*4+1] += xk * wd.y;
                accd[j4*4+2] += xk * wd.z; accd[j4*4+3] += xk * wd.w;
                accr[j4*4+0] += xk * wr.x; accr[j4*4+1] += xk * wr.y;
                accr[j4*4+2] += xk * wr.z; accr[j4*4+3] += xk * wr.w;
            }
        }
    }
    // interleaved pack: half[2j]=a0[j], half[2j+1]=ad[j]  (lane r gathers uint4 @ r*8)
    uint4 u0, u1, u2, u3;
    u0.x = pack_h2(acc0[0],  accd[0]);  u0.y = pack_h2(acc0[1],  accd[1]);
    u0.z = pack_h2(acc0[2],  accd[2]);  u0.w = pack_h2(acc0[3],  accd[3]);
    u1.x = pack_h2(acc0[4],  accd[4]);  u1.y = pack_h2(acc0[5],  accd[5]);
    u1.z = pack_h2(acc0[6],  accd[6]);  u1.w = pack_h2(acc0[7],  accd[7]);
    u2.x = pack_h2(acc0[8],  accd[8]);  u2.y = pack_h2(acc0[9],  accd[9]);
    u2.z = pack_h2(acc0[10], accd[10]); u2.w = pack_h2(acc0[11], accd[11]);
    u3.x = pack_h2(acc0[12], accd[12]); u3.y = pack_h2(acc0[13], accd[13]);
    u3.z = pack_h2(acc0[14], accd[14]); u3.w = pack_h2(acc0[15], accd[15]);
    uint4* dst = reinterpret_cast<uint4*>(&g_aqh[(size_t)n * 32]);
    dst[0] = u0; dst[1] = u1; dst[2] = u2; dst[3] = u3;

#pragma unroll
    for (int j4 = 0; j4 < HID / 4; j4++) {
        *reinterpret_cast<float4*>(&g_base1[(size_t)n * HID + j4 * 4]) =
            make_float4(accr[j4*4]   + b1[j4*4],   accr[j4*4+1] + b1[j4*4+1],
                        accr[j4*4+2] + b1[j4*4+2], accr[j4*4+3] + b1[j4*4+3]);
    }
}

// ---------------- layer-1 edge pass: 4 lanes/edge, ONE 16B gather per lane ---
__global__ void edge1_kernel(const int* __restrict__ ei,
                             const float* __restrict__ attr, int E)
{
    int t = blockIdx.x * blockDim.x + threadIdx.x;
    int e = t >> 2;
    int r = t & 3;
    if (e >= E) return;
    int   s = __ldg(&ei[e]);
    int   d = __ldg(&ei[E + e]);
    float w = __ldg(&attr[e]);

    uint4 g = __ldg(reinterpret_cast<const uint4*>(&g_aqh[(size_t)s * 32 + r * 8]));
    float2 p0 = __half22float2(*reinterpret_cast<__half2*>(&g.x));
    float2 p1 = __half22float2(*reinterpret_cast<__half2*>(&g.y));
    float2 p2 = __half22float2(*reinterpret_cast<__half2*>(&g.z));
    float2 p3 = __half22float2(*reinterpret_cast<__half2*>(&g.w));

    float4 msg = make_float4(fmaf(w, p0.y, p0.x), fmaf(w, p1.y, p1.x),
                             fmaf(w, p2.y, p2.x), fmaf(w, p3.y, p3.x));
    float* dstp = &g_agg1[(size_t)d * HID + r * 4];
    asm volatile("red.global.add.v4.f32 [%0], {%1,%2,%3,%4};"
                 :: "l"(dstp), "f"(msg.x), "f"(msg.y), "f"(msg.z), "f"(msg.w)
                 : "memory");
    if (r == 0) atomicAdd(&g_deg[d], 1.0f);
}

// ---------------- layer-1 finalize + ELU + layer-2 node transform ------------
__global__ __launch_bounds__(128)
void node2_kernel(const float* __restrict__ W2,
                  const float* __restrict__ root2,
                  const float* __restrict__ b2, int N)
{
    __shared__ float sB0[HID * CP];
    __shared__ float sBd[HID * CP];
    __shared__ float sR [HID * CP];
    __shared__ float sb2[CP];
    for (int i = threadIdx.x; i < HID * CP; i += blockDim.x) {
        int j = i / CP, c = i - j * CP;
        float w0 = (c < NC) ? W2[j * NC + c] : 0.f;
        float w1 = (c < NC) ? W2[HID * NC + j * NC + c] : 0.f;
        sB0[i] = w0;
        sBd[i] = w1 - w0;
        sR [i] = (c < NC) ? root2[j * NC + c] : 0.f;
    }
    if (threadIdx.x < CP) sb2[threadIdx.x] = (threadIdx.x < NC) ? b2[threadIdx.x] : 0.f;
    __syncthreads();

    int n = blockIdx.x * blockDim.x + threadIdx.x;
    if (n >= N) return;

    float inv = 1.f / fmaxf(g_deg[n], 1.f);
    float h[HID];
#pragma unroll
    for (int j4 = 0; j4 < HID / 4; j4++) {
        float4 ag = *reinterpret_cast<const float4*>(&g_agg1 [(size_t)n * HID + j4 * 4]);
        float4 bs = *reinterpret_cast<const float4*>(&g_base1[(size_t)n * HID + j4 * 4]);
        float v[4] = { ag.x * inv + bs.x, ag.y * inv + bs.y,
                       ag.z * inv + bs.z, ag.w * inv + bs.w };
#pragma unroll
        for (int q = 0; q < 4; q++)
            h[j4 * 4 + q] = (v[q] > 0.f) ? v[q] : expm1f(v[q]);
    }

    float o0[CP], od[CP], orr[CP];
#pragma unroll
    for (int c = 0; c < CP; c++) { o0[c] = 0.f; od[c] = 0.f; orr[c] = 0.f; }
#pragma unroll
    for (int j = 0; j < HID; j++) {
        float hj = h[j];
#pragma unroll
        for (int c4 = 0; c4 < CP / 4; c4++) {
            float4 w0 = *reinterpret_cast<const float4*>(&sB0[j * CP + c4 * 4]);
            float4 wd = *reinterpret_cast<const float4*>(&sBd[j * CP + c4 * 4]);
            float4 wr = *reinterpret_cast<const float4*>(&sR [j * CP + c4 * 4]);
            o0[c4*4+0] += hj * w0.x; o0[c4*4+1] += hj * w0.y;
            o0[c4*4+2] += hj * w0.z; o0[c4*4+3] += hj * w0.w;
            od[c4*4+0] += hj * wd.x; od[c4*4+1] += hj * wd.y;
            od[c4*4+2] += hj * wd.z; od[c4*4+3] += hj * wd.w;
            orr[c4*4+0] += hj * wr.x; orr[c4*4+1] += hj * wr.y;
            orr[c4*4+2] += hj * wr.z; orr[c4*4+3] += hj * wr.w;
        }
    }
    // interleaved pack: half[2c]=b0[c], half[2c+1]=bd[c], c=0..11
    uint4 u0, u1, u2;
    u0.x = pack_h2(o0[0],  od[0]);  u0.y = pack_h2(o0[1],  od[1]);
    u0.z = pack_h2(o0[2],  od[2]);  u0.w = pack_h2(o0[3],  od[3]);
    u1.x = pack_h2(o0[4],  od[4]);  u1.y = pack_h2(o0[5],  od[5]);
    u1.z = pack_h2(o0[6],  od[6]);  u1.w = pack_h2(o0[7],  od[7]);
    u2.x = pack_h2(o0[8],  od[8]);  u2.y = pack_h2(o0[9],  od[9]);
    u2.z = pack_h2(o0[10], od[10]); u2.w = pack_h2(o0[11], od[11]);
    uint4* dst = reinterpret_cast<uint4*>(&g_bqh[(size_t)n * 32]);
    dst[0] = u0; dst[1] = u1; dst[2] = u2;

#pragma unroll
    for (int c4 = 0; c4 < CP / 4; c4++) {
        *reinterpret_cast<float4*>(&g_base2[(size_t)n * CP + c4 * 4]) =
            make_float4(orr[c4*4]   + sb2[c4*4],   orr[c4*4+1] + sb2[c4*4+1],
                        orr[c4*4+2] + sb2[c4*4+2], orr[c4*4+3] + sb2[c4*4+3]);
    }
}

// ---------------- layer-2 edge pass: 3 lanes/edge, ONE 16B gather per lane ---
__global__ void edge2_kernel(const int* __restrict__ ei,
                             const float* __restrict__ attr, int E)
{
    int t    = blockIdx.x * blockDim.x + threadIdx.x;
    int warp = t >> 5;
    int lane = t & 31;
    if (lane >= 30) return;
    int el = lane / 3;                // 0..9
    int r  = lane - el * 3;           // 0..2
    int e  = warp * 10 + el;
    if (e >= E) return;

    int   s = __ldg(&ei[e]);
    int   d = __ldg(&ei[E + e]);
    float w = __ldg(&attr[e]);

    uint4 g = __ldg(reinterpret_cast<const uint4*>(&g_bqh[(size_t)s * 32 + r * 8]));
    float2 p0 = __half22float2(*reinterpret_cast<__half2*>(&g.x));
    float2 p1 = __half22float2(*reinterpret_cast<__half2*>(&g.y));
    float2 p2 = __half22float2(*reinterpret_cast<__half2*>(&g.z));
    float2 p3 = __half22float2(*reinterpret_cast<__half2*>(&g.w));

    float4 msg = make_float4(fmaf(w, p0.y, p0.x), fmaf(w, p1.y, p1.x),
                             fmaf(w, p2.y, p2.x), fmaf(w, p3.y, p3.x));
    float* dstp = &g_agg2[(size_t)d * CP + r * 4];
    asm volatile("red.global.add.v4.f32 [%0], {%1,%2,%3,%4};"
                 :: "l"(dstp), "f"(msg.x), "f"(msg.y), "f"(msg.z), "f"(msg.w)
                 : "memory");
}

// ---------------- output ----------------
__global__ void out_kernel(float* __restrict__ out, int N)
{
    int t = blockIdx.x * blockDim.x + threadIdx.x;
    if (t >= N * NC) return;
    int n = t / NC;
    int c = t - n * NC;
    float inv = 1.f / fmaxf(g_deg[n], 1.f);
    out[t] = g_agg2[(size_t)n * CP + c] * inv + g_base2[(size_t)n * CP + c];
}

// ---------------- launcher ----------------
extern "C" void kernel_launch(void* const* d_in, const int* in_sizes, int n_in,
                              void* d_out, int out_size)
{
    const float* x     = (const float*)d_in[0];
    const int*   ei    = (const int*)d_in[1];
    const float* attr  = (const float*)d_in[2];
    const float* W1    = (const float*)d_in[3];
    const float* root1 = (const float*)d_in[4];
    const float* b1    = (const float*)d_in[5];
    const float* W2    = (const float*)d_in[6];
    const float* root2 = (const float*)d_in[7];
    const float* b2    = (const float*)d_in[8];
    float*       out   = (float*)d_out;

    int N = in_sizes[0] / F_IN;
    int E = in_sizes[2];

    node1_kernel<<<(N + 127) / 128, 128>>>(x, W1, root1, b1, N);

    long long t1 = (long long)E * 4;
    edge1_kernel<<<(unsigned)((t1 + 255) / 256), 256>>>(ei, attr, E);

    node2_kernel<<<(N + 127) / 128, 128>>>(W2, root2, b2, N);

    long long nwarps = ((long long)E + 9) / 10;
    long long t2 = nwarps * 32;
    edge2_kernel<<<(unsigned)((t2 + 255) / 256), 256>>>(ei, attr, E);

    out_kernel<<<(N * NC + 255) / 256, 256>>>(out, N);
}